// round 4
// baseline (speedup 1.0000x reference)
#include <cuda_runtime.h>
#include <cuda_bf16.h>
#include <cstdint>

#define NAGENTS 32768
#define HDIM    256
#define ODIM    64
#define NGROUPS 1024
#define GSIZE   32
#define TSTEPS  (NAGENTS + 1)
#define ZROWS   1026   /* 1024 pooled + goal + zero-feat row */

// ---------------- device scratch (allocation-free) ----------------
__device__ float g_X[NAGENTS * HDIM];
__device__ float g_Y[NAGENTS * HDIM];
__device__ float g_R[ZROWS * HDIM];          // rows: pooled[0..1023], goal_emb, zeros
__device__ float g_zs[ZROWS * 1024];         // distinct input projections (+bias)
__device__ float g_hs[TSTEPS * HDIM];        // all hidden states
__device__ int   g_rowidx[NAGENTS];

// ---------------- PTX helpers ----------------
__device__ __forceinline__ uint32_t smem_u32(const void* p) {
    return (uint32_t)__cvta_generic_to_shared(p);
}
__device__ __forceinline__ uint32_t mapa_u32(uint32_t addr, uint32_t rank) {
    uint32_t r;
    asm("mapa.shared::cluster.u32 %0, %1, %2;" : "=r"(r) : "r"(addr), "r"(rank));
    return r;
}
__device__ __forceinline__ void st_async_b32(uint32_t daddr, uint32_t val, uint32_t dbar) {
    asm volatile("st.async.shared::cluster.mbarrier::complete_tx::bytes.b32 [%0], %1, [%2];"
                 :: "r"(daddr), "r"(val), "r"(dbar) : "memory");
}
__device__ __forceinline__ void mbar_init(uint32_t addr, uint32_t cnt) {
    asm volatile("mbarrier.init.shared.b64 [%0], %1;" :: "r"(addr), "r"(cnt) : "memory");
}
__device__ __forceinline__ void mbar_arrive_expect_tx(uint32_t addr, uint32_t bytes) {
    asm volatile("mbarrier.arrive.expect_tx.shared.b64 _, [%0], %1;"
                 :: "r"(addr), "r"(bytes) : "memory");
}
__device__ __forceinline__ void mbar_wait_cluster(uint32_t addr, uint32_t parity) {
    asm volatile(
        "{\n\t.reg .pred P;\n\t"
        "WL_%=:\n\t"
        "mbarrier.try_wait.parity.acquire.cluster.shared::cta.b64 P, [%0], %1, 0x989680;\n\t"
        "@P bra.uni WD_%=;\n\t"
        "bra.uni WL_%=;\n\t"
        "WD_%=:\n\t}"
        :: "r"(addr), "r"(parity) : "memory");
}
__device__ __forceinline__ uint32_t ctarank() {
    uint32_t r; asm("mov.u32 %0, %%cluster_ctarank;" : "=r"(r)); return r;
}
__device__ __forceinline__ float fsig(float x) {
    return __fdividef(1.0f, 1.0f + __expf(-x));
}
__device__ __forceinline__ float ftanh(float x) {
    float e = __expf(-2.0f * x);
    return __fdividef(1.0f - e, 1.0f + e);
}

// ---------------- goal embedding: R[1024] = relu(goal@W_goal+b); R[1025] = 0 ----------------
__global__ void k_goal(const float* __restrict__ goal, const float* __restrict__ W,
                       const float* __restrict__ b, float* __restrict__ R) {
    __shared__ float gs[HDIM];
    int j = threadIdx.x;
    gs[j] = goal[j];
    __syncthreads();
    float acc = 0.f;
    #pragma unroll 8
    for (int k = 0; k < HDIM; k++) acc = fmaf(gs[k], W[k * HDIM + j], acc);
    R[1024 * HDIM + j] = fmaxf(acc + b[j], 0.f);
    R[1025 * HDIM + j] = 0.f;
}

// ---------------- rowidx: default zero-row, scatter group ids ----------------
__global__ void k_rowidx_init(int* __restrict__ ri) {
    int i = blockIdx.x * blockDim.x + threadIdx.x;
    if (i < NAGENTS) ri[i] = 1025;
}
__global__ void k_rowidx_scatter(const int* __restrict__ groups, int* __restrict__ ri) {
    int e = blockIdx.x * blockDim.x + threadIdx.x;
    if (e < NGROUPS * GSIZE) ri[groups[e]] = e >> 5;
}

// ---------------- group aggregate: U[g*32+m] = (x_m + sum_members)/33 ----------------
// GATHER=1: input indexed via groups; GATHER=0: input already in gathered order.
template <int GATHER>
__global__ void k_group(const float* __restrict__ src, const int* __restrict__ groups,
                        float* __restrict__ U) {
    __shared__ float rows[GSIZE][HDIM];
    __shared__ int   idx[GSIZE];
    int g = blockIdx.x, t = threadIdx.x;
    if (GATHER) {
        if (t < GSIZE) idx[t] = groups[g * GSIZE + t];
        __syncthreads();
    }
    #pragma unroll 4
    for (int m = 0; m < GSIZE; m++) {
        int r = GATHER ? idx[m] : (g * GSIZE + m);
        rows[m][t] = src[r * HDIM + t];
    }
    __syncthreads();
    float s = 0.f;
    #pragma unroll
    for (int m = 0; m < GSIZE; m++) s += rows[m][t];
    const float inv = 1.0f / 33.0f;
    #pragma unroll 4
    for (int m = 0; m < GSIZE; m++)
        U[(g * GSIZE + m) * HDIM + t] = (rows[m][t] + s) * inv;
}

// ---------------- pooled[g] = mean over group of H2 ----------------
__global__ void k_pool(const float* __restrict__ H2, float* __restrict__ R) {
    int g = blockIdx.x, t = threadIdx.x;
    float s = 0.f;
    #pragma unroll
    for (int m = 0; m < GSIZE; m++) s += H2[(g * GSIZE + m) * HDIM + t];
    R[g * HDIM + t] = s * (1.0f / 32.0f);
}

// ---------------- tiled SGEMM: C = act(A[M,K]@B[K,N] + bias) ----------------
__global__ __launch_bounds__(256) void k_gemm(
    const float* __restrict__ A, const float* __restrict__ B,
    const float* __restrict__ bias, float* __restrict__ C,
    int M, int N, int K, int doRelu)
{
    __shared__ float As[64][20];   // [m][k], padded (80B rows keep 16B alignment)
    __shared__ float Bs[16][64];
    int t = threadIdx.x;
    int tx = t & 15, ty = t >> 4;
    int bm = blockIdx.y * 64, bn = blockIdx.x * 64;
    int row0 = ty * 4, col0 = tx * 4;
    float acc[4][4];
    #pragma unroll
    for (int i = 0; i < 4; i++)
        #pragma unroll
        for (int j = 0; j < 4; j++) acc[i][j] = 0.f;

    int am = t >> 2, ak4 = (t & 3) * 4;           // A tile: float4 per thread
    for (int kb = 0; kb < K; kb += 16) {
        float4 av = make_float4(0.f, 0.f, 0.f, 0.f);
        if (bm + am < M)
            av = *reinterpret_cast<const float4*>(&A[(size_t)(bm + am) * K + kb + ak4]);
        *reinterpret_cast<float4*>(&As[am][ak4]) = av;
        #pragma unroll
        for (int i = 0; i < 4; i++) {
            int e = t + i * 256;
            int k = e >> 6, n = e & 63;
            Bs[k][n] = B[(size_t)(kb + k) * N + bn + n];
        }
        __syncthreads();
        #pragma unroll
        for (int k = 0; k < 16; k++) {
            float a0 = As[row0 + 0][k], a1 = As[row0 + 1][k];
            float a2 = As[row0 + 2][k], a3 = As[row0 + 3][k];
            float4 bv = *reinterpret_cast<const float4*>(&Bs[k][col0]);
            acc[0][0] = fmaf(a0, bv.x, acc[0][0]); acc[0][1] = fmaf(a0, bv.y, acc[0][1]);
            acc[0][2] = fmaf(a0, bv.z, acc[0][2]); acc[0][3] = fmaf(a0, bv.w, acc[0][3]);
            acc[1][0] = fmaf(a1, bv.x, acc[1][0]); acc[1][1] = fmaf(a1, bv.y, acc[1][1]);
            acc[1][2] = fmaf(a1, bv.z, acc[1][2]); acc[1][3] = fmaf(a1, bv.w, acc[1][3]);
            acc[2][0] = fmaf(a2, bv.x, acc[2][0]); acc[2][1] = fmaf(a2, bv.y, acc[2][1]);
            acc[2][2] = fmaf(a2, bv.z, acc[2][2]); acc[2][3] = fmaf(a2, bv.w, acc[2][3]);
            acc[3][0] = fmaf(a3, bv.x, acc[3][0]); acc[3][1] = fmaf(a3, bv.y, acc[3][1]);
            acc[3][2] = fmaf(a3, bv.z, acc[3][2]); acc[3][3] = fmaf(a3, bv.w, acc[3][3]);
        }
        __syncthreads();
    }
    #pragma unroll
    for (int i = 0; i < 4; i++) {
        int r = bm + row0 + i;
        if (r >= M) break;
        #pragma unroll
        for (int j = 0; j < 4; j++) {
            float v = acc[i][j] + bias[bn + col0 + j];
            if (doRelu) v = fmaxf(v, 0.f);
            C[(size_t)r * N + bn + col0 + j] = v;
        }
    }
}

// ---------------- persistent 8-CTA-cluster LSTM ----------------
// CTA r owns hidden indices j in [r*32, r*32+32) and gate columns
// {g*256 + r*32 + j : g in 0..3}. W_hh slice lives in registers.
__global__ __launch_bounds__(512, 1) __cluster_dims__(8, 1, 1)
void k_lstm(const float* __restrict__ zs, const int* __restrict__ rowidx,
            const float* __restrict__ W_hh, float* __restrict__ hs)
{
    __shared__ __align__(16) float hbuf[2][HDIM];
    __shared__ float part[512];
    __shared__ float pa[128];
    __shared__ float hnew[32];
    __shared__ __align__(8) unsigned long long barr[2];

    const int t    = threadIdx.x;
    const int cl   = t & 127;          // local gate-column 0..127
    const int ks   = t >> 7;           // k-slice 0..3
    const int gate = cl >> 5;
    const int j    = cl & 31;
    const uint32_t rank = ctarank();
    const int base = rank * 32;
    const int gcol = gate * 256 + base + j;
    const int k0   = ks * 64;

    // resident W_hh slice: 64 regs/thread
    float w[64];
    #pragma unroll
    for (int kk = 0; kk < 64; kk++)
        w[kk] = W_hh[(size_t)(k0 + kk) * 1024 + gcol];

    if (t < HDIM) { hbuf[0][t] = 0.f; hbuf[1][t] = 0.f; }
    uint32_t bl0 = smem_u32(&barr[0]);
    uint32_t bl1 = smem_u32(&barr[1]);
    if (t == 0) {
        mbar_init(bl0, 1); mbar_init(bl1, 1);
        mbar_arrive_expect_tx(bl0, 1024);   // arm phase 0 of each barrier
        mbar_arrive_expect_tx(bl1, 1024);
        asm volatile("fence.mbarrier_init.release.cluster;" ::: "memory");
    }
    __syncthreads();
    asm volatile("barrier.cluster.arrive.aligned;" ::: "memory");
    asm volatile("barrier.cluster.wait.aligned;" ::: "memory");

    // precomputed remote addresses for broadcast (threads 0..255: rank=t>>5, slot=t&31)
    uint32_t rd0 = 0, rd1 = 0, rb0 = 0, rb1 = 0;
    if (t < 256) {
        uint32_t dr = t >> 5;
        rd0 = mapa_u32(smem_u32(&hbuf[0][base + (t & 31)]), dr);
        rd1 = mapa_u32(smem_u32(&hbuf[1][base + (t & 31)]), dr);
        rb0 = mapa_u32(bl0, dr);
        rb1 = mapa_u32(bl1, dr);
    }

    float c = 0.f;                     // cell state (threads 0..31)
    uint32_t ph0 = 0, ph1 = 0;

    for (int step = 0; step < TSTEPS; step++) {
        // prefetch this step's input projection (off the critical path)
        float zval = 0.f;
        if (t < 128) {
            int row = (step == NAGENTS) ? 1024 : __ldg(&rowidx[step]);
            zval = __ldg(&zs[(size_t)row * 1024 + gcol]);
        }

        const int buf = step & 1;
        if (step > 0) {                // wait for h(step-1) all-gather
            if (buf) { mbar_wait_cluster(bl1, ph1); ph1 ^= 1; }
            else     { mbar_wait_cluster(bl0, ph0); ph0 ^= 1; }
            if (t == 0) mbar_arrive_expect_tx(buf ? bl1 : bl0, 1024);  // re-arm next phase
        }

        // matvec slice: acc = sum_k h[k0+kk]*w[kk]
        const float4* hp = reinterpret_cast<const float4*>(&hbuf[buf][k0]);
        float a0 = 0.f, a1 = 0.f;
        #pragma unroll
        for (int q = 0; q < 16; q += 2) {
            float4 h4 = hp[q];
            a0 = fmaf(h4.x, w[4*q+0], a0); a0 = fmaf(h4.y, w[4*q+1], a0);
            a0 = fmaf(h4.z, w[4*q+2], a0); a0 = fmaf(h4.w, w[4*q+3], a0);
            float4 h5 = hp[q+1];
            a1 = fmaf(h5.x, w[4*q+4], a1); a1 = fmaf(h5.y, w[4*q+5], a1);
            a1 = fmaf(h5.z, w[4*q+6], a1); a1 = fmaf(h5.w, w[4*q+7], a1);
        }
        part[t] = a0 + a1;
        __syncthreads();

        if (t < 128)
            pa[t] = part[t] + part[t + 128] + part[t + 256] + part[t + 384] + zval;
        __syncthreads();

        if (t < 32) {
            float zi = pa[t], zf = pa[32 + t], zg = pa[64 + t], zo = pa[96 + t];
            c = fsig(zf) * c + fsig(zi) * ftanh(zg);
            float h = fsig(zo) * ftanh(c);
            hnew[t] = h;
            hs[step * HDIM + base + t] = h;
        }
        __syncthreads();

        if (t < 256 && step + 1 < TSTEPS) {   // all-gather h into buf (step+1)&1
            uint32_t val = __float_as_uint(hnew[t & 31]);
            if ((step + 1) & 1) st_async_b32(rd1, val, rb1);
            else                st_async_b32(rd0, val, rb0);
        }
    }
}

// ---------------- output: softmax(hs@W_act + b_act) ----------------
__global__ __launch_bounds__(256) void k_out(const float* __restrict__ hs,
                                             const float* __restrict__ W,
                                             const float* __restrict__ b,
                                             float* __restrict__ out) {
    __shared__ float hrow[8][HDIM];
    int warp = threadIdx.x >> 5, lane = threadIdx.x & 31;
    int row = blockIdx.x * 8 + warp;
    if (row >= TSTEPS) return;
    #pragma unroll
    for (int q = 0; q < 8; q++)
        hrow[warp][lane + q * 32] = hs[row * HDIM + lane + q * 32];
    __syncwarp();
    int c0 = lane, c1 = lane + 32;
    float acc0 = b[c0], acc1 = b[c1];
    #pragma unroll 8
    for (int k = 0; k < HDIM; k++) {
        float h = hrow[warp][k];
        acc0 = fmaf(h, __ldg(&W[k * ODIM + c0]), acc0);
        acc1 = fmaf(h, __ldg(&W[k * ODIM + c1]), acc1);
    }
    float m = fmaxf(acc0, acc1);
    #pragma unroll
    for (int s = 16; s > 0; s >>= 1) m = fmaxf(m, __shfl_xor_sync(0xffffffffu, m, s));
    float e0 = __expf(acc0 - m), e1 = __expf(acc1 - m);
    float s = e0 + e1;
    #pragma unroll
    for (int d = 16; d > 0; d >>= 1) s += __shfl_xor_sync(0xffffffffu, s, d);
    float inv = __fdividef(1.0f, s);
    out[row * ODIM + c0] = e0 * inv;
    out[row * ODIM + c1] = e1 * inv;
}

// ---------------- launch ----------------
extern "C" void kernel_launch(void* const* d_in, const int* in_sizes, int n_in,
                              void* d_out, int out_size) {
    const float* agent_state = (const float*)d_in[0];
    const float* goal_state  = (const float*)d_in[1];
    const int*   groups      = (const int*)  d_in[2];
    const float* W_goal      = (const float*)d_in[3];
    const float* b_goal      = (const float*)d_in[4];
    const float* W_g1        = (const float*)d_in[5];
    const float* b_g1        = (const float*)d_in[6];
    const float* W_g2        = (const float*)d_in[7];
    const float* b_g2        = (const float*)d_in[8];
    const float* W_ih        = (const float*)d_in[9];
    const float* W_hh        = (const float*)d_in[10];
    const float* b_lstm      = (const float*)d_in[11];
    const float* W_act       = (const float*)d_in[12];
    const float* b_act       = (const float*)d_in[13];
    float* out = (float*)d_out;

    float *X, *Y, *R, *ZS, *HS; int* RI;
    cudaGetSymbolAddress((void**)&X,  g_X);
    cudaGetSymbolAddress((void**)&Y,  g_Y);
    cudaGetSymbolAddress((void**)&R,  g_R);
    cudaGetSymbolAddress((void**)&ZS, g_zs);
    cudaGetSymbolAddress((void**)&HS, g_hs);
    cudaGetSymbolAddress((void**)&RI, g_rowidx);

    k_goal<<<1, 256>>>(goal_state, W_goal, b_goal, R);
    k_rowidx_init<<<NAGENTS / 256, 256>>>(RI);
    k_rowidx_scatter<<<NGROUPS * GSIZE / 256, 256>>>(groups, RI);

    k_group<1><<<NGROUPS, 256>>>(agent_state, groups, X);                 // U1
    k_gemm<<<dim3(4, 512), 256>>>(X, W_g1, b_g1, Y, NAGENTS, HDIM, HDIM, 1);   // H1
    k_group<0><<<NGROUPS, 256>>>(Y, nullptr, X);                          // U2
    k_gemm<<<dim3(4, 512), 256>>>(X, W_g2, b_g2, Y, NAGENTS, HDIM, HDIM, 1);   // H2
    k_pool<<<NGROUPS, 256>>>(Y, R);

    k_gemm<<<dim3(16, 17), 256>>>(R, W_ih, b_lstm, ZS, ZROWS, 1024, HDIM, 0);  // zs

    k_lstm<<<8, 512>>>(ZS, RI, W_hh, HS);

    k_out<<<(TSTEPS + 7) / 8, 256>>>(HS, W_act, b_act, out);
}